// round 11
// baseline (speedup 1.0000x reference)
#include <cuda_runtime.h>
#include <cuda_bf16.h>
#include <cuda_fp16.h>
#include <math.h>
#include <stdint.h>

#define Bq   512
#define Sq   128
#define NEq  8192
#define EDq  128
#define DDq  32
#define NDq  8
#define HHq  512
#define PLq  5
#define G4q  2048   // 4*H

// ================= warp-MMA helpers (portable PTX: sm_80+) =================
__device__ __forceinline__ uint32_t smem_u32(const void* p) {
    uint32_t a;
    asm("{ .reg .u64 t; cvta.to.shared.u64 t, %1; cvt.u32.u64 %0, t; }" : "=r"(a) : "l"(p));
    return a;
}

__device__ __forceinline__ void ldsm_x4(uint32_t& r0, uint32_t& r1, uint32_t& r2, uint32_t& r3, uint32_t addr) {
    asm volatile("ldmatrix.sync.aligned.m8n8.x4.shared.b16 {%0,%1,%2,%3}, [%4];"
        : "=r"(r0), "=r"(r1), "=r"(r2), "=r"(r3) : "r"(addr));
}
// bf16 MMA (used by the generic GEMM)
__device__ __forceinline__ void mma16816(float* c, uint32_t a0, uint32_t a1, uint32_t a2, uint32_t a3,
                                         uint32_t b0, uint32_t b1) {
    asm volatile(
        "mma.sync.aligned.m16n8k16.row.col.f32.bf16.bf16.f32 "
        "{%0,%1,%2,%3}, {%4,%5,%6,%7}, {%8,%9}, {%0,%1,%2,%3};"
        : "+f"(c[0]), "+f"(c[1]), "+f"(c[2]), "+f"(c[3])
        : "r"(a0), "r"(a1), "r"(a2), "r"(a3), "r"(b0), "r"(b1));
}
// fp16 MMA (LSTM)
__device__ __forceinline__ void mma16816h(float* c, uint32_t a0, uint32_t a1, uint32_t a2, uint32_t a3,
                                          uint32_t b0, uint32_t b1) {
    asm volatile(
        "mma.sync.aligned.m16n8k16.row.col.f32.f16.f16.f32 "
        "{%0,%1,%2,%3}, {%4,%5,%6,%7}, {%8,%9}, {%0,%1,%2,%3};"
        : "+f"(c[0]), "+f"(c[1]), "+f"(c[2]), "+f"(c[3])
        : "r"(a0), "r"(a1), "r"(a2), "r"(a3), "r"(b0), "r"(b1));
}
__device__ __forceinline__ void cp_async16(uint32_t dst, const void* src) {
    asm volatile("cp.async.cg.shared.global [%0], [%1], 16;" :: "r"(dst), "l"(src) : "memory");
}
#define CP_COMMIT() asm volatile("cp.async.commit_group;" ::: "memory")

// split fp32 -> (hi, lo) bf16 pair packed as bf16x2 words
__device__ __forceinline__ void split_pack(float x, float y,
                                           uint32_t& hi, uint32_t& lo) {
    __nv_bfloat16 hx = __float2bfloat16(x);
    __nv_bfloat16 hy = __float2bfloat16(y);
    __nv_bfloat16 lx = __float2bfloat16(x - __bfloat162float(hx));
    __nv_bfloat16 ly = __float2bfloat16(y - __bfloat162float(hy));
    __nv_bfloat162 h2; h2.x = hx; h2.y = hy;
    __nv_bfloat162 l2; l2.x = lx; l2.y = ly;
    hi = *(uint32_t*)&h2;
    lo = *(uint32_t*)&l2;
}
// split fp32 -> (hi, lo) fp16 pair packed as half2 words
__device__ __forceinline__ void split_pack_h(float x, float y,
                                             uint32_t& hi, uint32_t& lo) {
    __half hx = __float2half(x);
    __half hy = __float2half(y);
    __half lx = __float2half(x - __half2float(hx));
    __half ly = __float2half(y - __half2float(hy));
    __half2 h2; h2.x = hx; h2.y = hy;
    __half2 l2; l2.x = lx; l2.y = ly;
    hi = *(uint32_t*)&h2;
    lo = *(uint32_t*)&l2;
}

// ================= scratch (static device globals) =================
__device__ float g_linkproj[(NEq + 1) * G4q];   // 67 MB
__device__ float g_dirproj[(NDq + 1) * G4q];
__device__ __align__(16) __half g_hh[2][Bq * HHq];  // h (fp16), double buffered
__device__ float g_c[Bq * HHq];
__device__ float g_hfinal[Bq * HHq];
__device__ float g_z1[Bq * HHq];
__device__ float g_z2[Bq * HHq];
__device__ float g_query[Bq * EDq];
__device__ float g_rowloss[Bq];
__device__ int   g_rowcorrect[Bq];
__device__ __align__(16) int g_flags[4][32];    // [batch group][dim CTA]: published h step

__device__ __forceinline__ float sigmoidf_(float x) { return 1.0f / (1.0f + expf(-x)); }

// single-thread poll: 4 producer flags (one 16B quad) until all >= t, then acquire fence
__device__ __forceinline__ void poll4(const int* f, int t) {
    while (true) {
        int4 v;
        asm volatile("ld.volatile.global.v4.s32 {%0,%1,%2,%3}, [%4];"
            : "=r"(v.x), "=r"(v.y), "=r"(v.z), "=r"(v.w) : "l"(f) : "memory");
        if (v.x >= t && v.y >= t && v.z >= t && v.w >= t) break;
        __nanosleep(32);
    }
    asm volatile("fence.acq_rel.gpu;" ::: "memory");
}

// ---------------- init: zero h0, c, flags ----------------
__global__ void init_kernel() {
    int i = blockIdx.x * blockDim.x + threadIdx.x;
    if (i < 4 * 32) ((int*)g_flags)[i] = 0;
    if (i < Bq * HHq) {
        g_c[i] = 0.0f;
        g_hh[0][i] = __float2half(0.0f);
    }
}

// ---------------- dir projection (+ both biases) ----------------
__global__ void dirproj_kernel(const float* __restrict__ dir_emb,
                               const float* __restrict__ w_ih,
                               const float* __restrict__ b_ih,
                               const float* __restrict__ b_hh)
{
    int i = blockIdx.x * blockDim.x + threadIdx.x;
    if (i >= (NDq + 1) * G4q) return;
    int e = i / G4q;
    int n = i % G4q;
    float s = b_ih[n] + b_hh[n];
#pragma unroll
    for (int k = 0; k < DDq; k++)
        s = fmaf(dir_emb[e * DDq + k], w_ih[n * (EDq + DDq) + EDq + k], s);
    g_dirproj[i] = s;
}

// ================= tensor GEMM, K multiple of 128, 3-term bf16 split =================
// C[M,N] = act(A[M,K] @ W[N,K]^T + bias) ; replicated store (reps, repstride)
// block tile 128x64, 8 warps (4m x 2n), warp tile 32x32
#define GK_AHI 0
#define GK_ALO 34816
#define GK_WHI 69632
#define GK_WLO 87040
#define GK_TOTAL 104448
// row strides: 136 bf16 (272B)

__global__ __launch_bounds__(256, 1) void mma_gemm128_kernel(
    const float* __restrict__ A, int lda,
    const float* __restrict__ W, int ldw,
    const float* __restrict__ bias,
    float* __restrict__ C, long long ldc,
    int M, int K, int relu, int reps, long long repstride)
{
    extern __shared__ char sm[];
    const int tid = threadIdx.x;
    const int lane = tid & 31;
    const int wid = tid >> 5;
    const int moff = (wid >> 1) * 32;
    const int noff = (wid & 1) * 32;
    const int mbase = blockIdx.x * 128;
    const int nbase = blockIdx.y * 64;

    float acc[2][4][4];
#pragma unroll
    for (int mt = 0; mt < 2; mt++)
#pragma unroll
        for (int nt = 0; nt < 4; nt++)
#pragma unroll
            for (int r = 0; r < 4; r++) acc[mt][nt][r] = 0.0f;

    const uint32_t smbase = smem_u32(sm);
    const uint32_t aoff = (moff + (lane & 15)) * 272 + (lane >> 4) * 16;
    const uint32_t boff = (noff + ((lane >> 4) & 1) * 8 + (lane & 7)) * 272 + ((lane >> 3) & 1) * 16;

    for (int kb = 0; kb < K; kb += 128) {
        // load + split A tile [128 x 128]
#pragma unroll
        for (int it = 0; it < 16; it++) {
            int idx = tid + it * 256;       // 0..4095
            int r = idx >> 5, q = idx & 31;
            int gm = mbase + r;
            float4 v = (gm < M) ? *(const float4*)(A + (long long)gm * lda + kb + q * 4)
                                : make_float4(0.f, 0.f, 0.f, 0.f);
            uint32_t h0, l0, h1, l1;
            split_pack(v.x, v.y, h0, l0);
            split_pack(v.z, v.w, h1, l1);
            int byte = r * 272 + q * 8;
            *(uint32_t*)(sm + GK_AHI + byte)     = h0;
            *(uint32_t*)(sm + GK_AHI + byte + 4) = h1;
            *(uint32_t*)(sm + GK_ALO + byte)     = l0;
            *(uint32_t*)(sm + GK_ALO + byte + 4) = l1;
        }
        // load + split W tile [64 x 128]
#pragma unroll
        for (int it = 0; it < 8; it++) {
            int idx = tid + it * 256;       // 0..2047
            int j = idx >> 5, q = idx & 31;
            int gn = nbase + j;
            float4 v = *(const float4*)(W + (long long)gn * ldw + kb + q * 4);
            uint32_t h0, l0, h1, l1;
            split_pack(v.x, v.y, h0, l0);
            split_pack(v.z, v.w, h1, l1);
            int byte = j * 272 + q * 8;
            *(uint32_t*)(sm + GK_WHI + byte)     = h0;
            *(uint32_t*)(sm + GK_WHI + byte + 4) = h1;
            *(uint32_t*)(sm + GK_WLO + byte)     = l0;
            *(uint32_t*)(sm + GK_WLO + byte + 4) = l1;
        }
        __syncthreads();

#pragma unroll
        for (int kk = 0; kk < 8; kk++) {
            uint32_t ah[2][4], al[2][4];
#pragma unroll
            for (int mt = 0; mt < 2; mt++) {
                uint32_t addr = smbase + GK_AHI + aoff + mt * (16 * 272) + kk * 32;
                ldsm_x4(ah[mt][0], ah[mt][1], ah[mt][2], ah[mt][3], addr);
                ldsm_x4(al[mt][0], al[mt][1], al[mt][2], al[mt][3], addr + (GK_ALO - GK_AHI));
            }
            uint32_t bh[4][2], bl[4][2];
#pragma unroll
            for (int p = 0; p < 2; p++) {
                uint32_t addr = smbase + GK_WHI + boff + p * (16 * 272) + kk * 32;
                ldsm_x4(bh[2 * p][0], bh[2 * p][1], bh[2 * p + 1][0], bh[2 * p + 1][1], addr);
                ldsm_x4(bl[2 * p][0], bl[2 * p][1], bl[2 * p + 1][0], bl[2 * p + 1][1], addr + (GK_WLO - GK_WHI));
            }
#pragma unroll
            for (int mt = 0; mt < 2; mt++)
#pragma unroll
                for (int nt = 0; nt < 4; nt++) {
                    mma16816(acc[mt][nt], ah[mt][0], ah[mt][1], ah[mt][2], ah[mt][3], bh[nt][0], bh[nt][1]);
                    mma16816(acc[mt][nt], al[mt][0], al[mt][1], al[mt][2], al[mt][3], bh[nt][0], bh[nt][1]);
                    mma16816(acc[mt][nt], ah[mt][0], ah[mt][1], ah[mt][2], ah[mt][3], bl[nt][0], bl[nt][1]);
                }
        }
        __syncthreads();
    }

    // store
    const int g = lane >> 2, tg = lane & 3;
#pragma unroll
    for (int mt = 0; mt < 2; mt++) {
#pragma unroll
        for (int nt = 0; nt < 4; nt++) {
            int col = nbase + noff + nt * 8 + tg * 2;
            int r0 = mbase + moff + mt * 16 + g;
            int r1 = r0 + 8;
            float v0 = acc[mt][nt][0], v1 = acc[mt][nt][1];
            float v2 = acc[mt][nt][2], v3 = acc[mt][nt][3];
            if (bias) {
                float b0 = bias[col], b1v = bias[col + 1];
                v0 += b0; v1 += b1v; v2 += b0; v3 += b1v;
            }
            if (relu) {
                v0 = fmaxf(v0, 0.f); v1 = fmaxf(v1, 0.f);
                v2 = fmaxf(v2, 0.f); v3 = fmaxf(v3, 0.f);
            }
            for (int rp = 0; rp < reps; rp++) {
                long long base = (long long)rp * repstride;
                if (r0 < M) {
                    C[(long long)r0 * ldc + base + col]     = v0;
                    C[(long long)r0 * ldc + base + col + 1] = v1;
                }
                if (r1 < M) {
                    C[(long long)r1 * ldc + base + col]     = v2;
                    C[(long long)r1 * ldc + base + col + 1] = v3;
                }
            }
        }
    }
}

// ================= persistent warp-MMA LSTM (fp16 2-term, flag-pipelined) =================
// grid (4, 32): blockIdx.x -> 128 batch rows, blockIdx.y -> 16 hidden dims (64 gate cols)
// 512 threads, 16 warps as 4m x 2n x 2k (warp tile 32x32 over half of each 64-k chunk)
// Sync: per-chunk producer flags. Chunk c of step t reads h dims 64c..64c+63, produced by
// CTAs by=4c..4c+3 of the same batch group. tid0 polls the flag quad for chunk c+3 during
// chunk c (prologue covers 0..2); the existing chunk-top __syncthreads joins the poll.
// smem: B_hi[64x520 fp16] | B_lo | A: 3 stages x 16KB (hi only), swizzled 128B rows
//       (A region reused for two fp32 partial-gate regions [128x68])
#define LS_BHI   0
#define LS_BLO   66560
#define LS_A     133120
#define LS_GATES 133120
#define LS_GSTR  34816      // bytes per partial-gate region (128 * 68 * 4)
#define LS_TOTAL 202752

__global__ __launch_bounds__(512, 1) void lstm_persist_kernel(
    const int* __restrict__ inputs,
    const int* __restrict__ directions,
    const float* __restrict__ w_hh)
{
    extern __shared__ char sm[];
    const int tid = threadIdx.x;
    const int lane = tid & 31;
    const int wid = tid >> 5;
    const int moff = (wid >> 2) * 32;          // 4 m groups
    const int noff = ((wid >> 1) & 1) * 32;    // 2 n groups
    const int kslice = wid & 1;                // 2 k slices
    const int bbase = blockIdx.x * 128;
    const int dbase = blockIdx.y * 16;
    const int* myflags = &g_flags[blockIdx.x][0];

    // ---- convert w_hh slice into persistent smem (fp16 hi/lo) ----
#pragma unroll
    for (int it = 0; it < 16; it++) {
        int idx = tid + it * 512;       // 0..8191
        int j = idx >> 7;               // gate row 0..63
        int kq = idx & 127;             // float4 index
        int gr = (j >> 4) * HHq + dbase + (j & 15);
        float4 v = *(const float4*)(w_hh + (long long)gr * HHq + kq * 4);
        uint32_t h0, l0, h1, l1;
        split_pack_h(v.x, v.y, h0, l0);
        split_pack_h(v.z, v.w, h1, l1);
        int byte = j * 1040 + kq * 8;
        *(uint32_t*)(sm + LS_BHI + byte)     = h0;
        *(uint32_t*)(sm + LS_BHI + byte + 4) = h1;
        *(uint32_t*)(sm + LS_BLO + byte)     = l0;
        *(uint32_t*)(sm + LS_BLO + byte + 4) = l1;
    }
    __syncthreads();

    const uint32_t smbase = smem_u32(sm);
    const uint32_t boff = (noff + ((lane >> 4) & 1) * 8 + (lane & 7)) * 1040 + ((lane >> 3) & 1) * 16;
    const int g = lane >> 2, tg = lane & 3;
    // A staging: 1024 16B units per chunk, 2 per thread (swizzled rows)
    const int sm0 = tid >> 3, su0 = tid & 7;
    const int sm1 = (tid + 512) >> 3, su1 = (tid + 512) & 7;
    const uint32_t sw0 = sm0 * 128 + (((su0 ^ (sm0 & 7)) & 7) << 4);
    const uint32_t sw1 = sm1 * 128 + (((su1 ^ (sm1 & 7)) & 7) << 4);
    // A ldmatrix swizzled addressing pieces
    const int arow = lane & 15;
    const int aunit = lane >> 4;
    const int axor = lane & 7;

    for (int t = 0; t < Sq; t++) {
        const __half* __restrict__ hh = g_hh[t & 1];

        // ---- prologue: wait producers of chunks 0..2, then issue chunks 0,1 ----
        if (tid == 0 && t > 0) {
            poll4(myflags + 0, t);
            poll4(myflags + 4, t);
            poll4(myflags + 8, t);
        }
        __syncthreads();
#pragma unroll
        for (int pc = 0; pc < 2; pc++) {
            uint32_t hi_off = LS_A + (uint32_t)(pc % 3) * 16384u;
            cp_async16(smbase + hi_off + sw0, hh + (long long)(bbase + sm0) * HHq + pc * 64 + su0 * 8);
            cp_async16(smbase + hi_off + sw1, hh + (long long)(bbase + sm1) * HHq + pc * 64 + su1 * 8);
            CP_COMMIT();
        }

        // ---- init accumulators: kslice 0 from linkproj+dirproj, kslice 1 zero ----
        float acc[2][4][4];
        if (kslice == 0) {
#pragma unroll
            for (int mt = 0; mt < 2; mt++) {
#pragma unroll
                for (int ph = 0; ph < 2; ph++) {
                    int row = moff + mt * 16 + g + ph * 8;
                    int b = bbase + row;
                    int L  = inputs[b * Sq + t];
                    int Dp = directions[b * Sq + t];
                    const float* lrow = g_linkproj + (long long)L * G4q;
                    const float* drow = g_dirproj + Dp * G4q;
#pragma unroll
                    for (int nt = 0; nt < 4; nt++) {
                        int j = noff + nt * 8 + tg * 2;
                        int gidx = (j >> 4) * HHq + dbase + (j & 15);
                        float2 lv = *(const float2*)(lrow + gidx);
                        float2 dv = *(const float2*)(drow + gidx);
                        acc[mt][nt][ph * 2 + 0] = lv.x + dv.x;
                        acc[mt][nt][ph * 2 + 1] = lv.y + dv.y;
                    }
                }
            }
        } else {
#pragma unroll
            for (int mt = 0; mt < 2; mt++)
#pragma unroll
                for (int nt = 0; nt < 4; nt++)
#pragma unroll
                    for (int r = 0; r < 4; r++) acc[mt][nt][r] = 0.0f;
        }

        for (int c = 0; c < 8; c++) {
            if (c < 7) asm volatile("cp.async.wait_group 1;" ::: "memory");
            else       asm volatile("cp.async.wait_group 0;" ::: "memory");

            // poll producers of chunk c+3 (consumed when chunk c+3 is issued next iteration)
            if (tid == 0 && t > 0 && c + 3 < 8)
                poll4(myflags + (c + 3) * 4, t);
            __syncthreads();

            // issue chunk c+2 into buffer (c+2)%3 (producers polled last iteration / prologue)
            if (c + 2 < 8) {
                int nc = c + 2;
                uint32_t hi_off = LS_A + (uint32_t)(nc % 3) * 16384u;
                cp_async16(smbase + hi_off + sw0, hh + (long long)(bbase + sm0) * HHq + nc * 64 + su0 * 8);
                cp_async16(smbase + hi_off + sw1, hh + (long long)(bbase + sm1) * HHq + nc * 64 + su1 * 8);
                CP_COMMIT();
            }

            const uint32_t a_hi = LS_A + (uint32_t)(c % 3) * 16384u;
            const uint32_t b_addr0 = smbase + LS_BHI + boff + c * 128;

            // this warp's half of the 4 k16 slices in this chunk
#pragma unroll
            for (int kk2 = 0; kk2 < 2; kk2++) {
                const int kk = kslice * 2 + kk2;
                uint32_t ah[2][4];
#pragma unroll
                for (int mt = 0; mt < 2; mt++) {
                    uint32_t addr = smbase + a_hi
                        + (uint32_t)(moff + mt * 16 + arow) * 128u
                        + (uint32_t)(((kk * 2 + aunit) ^ axor) << 4);
                    ldsm_x4(ah[mt][0], ah[mt][1], ah[mt][2], ah[mt][3], addr);
                }
#pragma unroll
                for (int p = 0; p < 2; p++) {
                    uint32_t bh2[2][2], bl2[2][2];
                    uint32_t addr = b_addr0 + p * (16 * 1040) + kk * 32;
                    ldsm_x4(bh2[0][0], bh2[0][1], bh2[1][0], bh2[1][1], addr);
                    ldsm_x4(bl2[0][0], bl2[0][1], bl2[1][0], bl2[1][1], addr + (LS_BLO - LS_BHI));
#pragma unroll
                    for (int mt = 0; mt < 2; mt++)
#pragma unroll
                        for (int nl = 0; nl < 2; nl++) {
                            float* a = acc[mt][p * 2 + nl];
                            mma16816h(a, ah[mt][0], ah[mt][1], ah[mt][2], ah[mt][3], bh2[nl][0], bh2[nl][1]);
                            mma16816h(a, ah[mt][0], ah[mt][1], ah[mt][2], ah[mt][3], bl2[nl][0], bl2[nl][1]);
                        }
                }
            }
        }
        __syncthreads();   // all MMA reads of A buffers done before gate-region overwrite

        // ---- stage partial gates into smem: region per kslice ----
        float* gsm = (float*)(sm + LS_GATES + kslice * LS_GSTR);
#pragma unroll
        for (int mt = 0; mt < 2; mt++)
#pragma unroll
            for (int nt = 0; nt < 4; nt++) {
                int row = moff + mt * 16 + g;
                int col = noff + nt * 8 + tg * 2;
                gsm[row * 68 + col]           = acc[mt][nt][0];
                gsm[row * 68 + col + 1]       = acc[mt][nt][1];
                gsm[(row + 8) * 68 + col]     = acc[mt][nt][2];
                gsm[(row + 8) * 68 + col + 1] = acc[mt][nt][3];
            }
        __syncthreads();

        // ---- elementwise LSTM update (2048 cells / 512 threads); sum both k partials ----
        float* g0 = (float*)(sm + LS_GATES);
        float* g1 = (float*)(sm + LS_GATES + LS_GSTR);
        __half* __restrict__ hho = g_hh[(t + 1) & 1];
#pragma unroll
        for (int q = 0; q < 4; q++) {
            int p = tid + 512 * q;          // 0..2047
            int m = p >> 4, dd = p & 15;
            int b = bbase + m;
            int gi = dbase + dd;
            float iv = g0[m * 68 + dd]      + g1[m * 68 + dd];
            float fv = g0[m * 68 + 16 + dd] + g1[m * 68 + 16 + dd];
            float gv = g0[m * 68 + 32 + dd] + g1[m * 68 + 32 + dd];
            float ov = g0[m * 68 + 48 + dd] + g1[m * 68 + 48 + dd];
            long long ci = (long long)b * HHq + gi;
            float cc = g_c[ci];
            float cn = sigmoidf_(fv) * cc + sigmoidf_(iv) * tanhf(gv);
            g_c[ci] = cn;
            float hv = sigmoidf_(ov) * tanhf(cn);
            hho[ci] = __float2half(hv);
            if (t == Sq - 1) g_hfinal[ci] = hv;
        }

        // ---- publish: all h writes visible, then release this CTA's flag ----
        if (t < Sq - 1) {
            __threadfence();
            __syncthreads();
            if (tid == 0)
                *((volatile int*)&g_flags[blockIdx.x][blockIdx.y]) = t + 1;
        }
    }
}

// ---------------- per-row head: logits, log-softmax x2, top-2, label, query ----------------
__global__ void rowhead_kernel(const int* __restrict__ inputs,
                               const int* __restrict__ goal,
                               const int* __restrict__ ldm,
                               const float* __restrict__ W3,
                               const float* __restrict__ b3,
                               const float* __restrict__ link_emb,
                               const float* __restrict__ dir_emb)
{
    int b = blockIdx.x;
    __shared__ float zrow[HHq];
    __shared__ float red[NDq][64];
    __shared__ float lg[NDq];
    __shared__ int sidx[2];
    __shared__ int slast;

    const float* z = g_z2 + b * HHq;
    for (int i = threadIdx.x; i < HHq; i += 64) zrow[i] = z[i];
    __syncthreads();

    float part[NDq];
#pragma unroll
    for (int o = 0; o < NDq; o++) part[o] = 0.0f;
    for (int k = threadIdx.x; k < HHq; k += 64) {
        float zv = zrow[k];
#pragma unroll
        for (int o = 0; o < NDq; o++) part[o] = fmaf(zv, W3[o * HHq + k], part[o]);
    }
#pragma unroll
    for (int o = 0; o < NDq; o++) red[o][threadIdx.x] = part[o];
    __syncthreads();

    if (threadIdx.x < NDq) {
        int o = threadIdx.x;
        float s = 0.0f;
        for (int i = 0; i < 64; i++) s += red[o][i];
        lg[o] = s + b3[o];
    }
    __syncthreads();

    if (threadIdx.x == 0) {
        float mx = lg[0];
#pragma unroll
        for (int o = 1; o < NDq; o++) mx = fmaxf(mx, lg[o]);
        float se = 0.0f;
#pragma unroll
        for (int o = 0; o < NDq; o++) se += expf(lg[o] - mx);
        float lse = mx + logf(se);
        float p[NDq];
#pragma unroll
        for (int o = 0; o < NDq; o++) p[o] = lg[o] - lse;
        float mx2 = p[0];
#pragma unroll
        for (int o = 1; o < NDq; o++) mx2 = fmaxf(mx2, p[o]);
        float se2 = 0.0f;
#pragma unroll
        for (int o = 0; o < NDq; o++) se2 += expf(p[o] - mx2);
        float lse2 = mx2 + logf(se2);
        int i0 = 0;
#pragma unroll
        for (int o = 1; o < NDq; o++) if (p[o] > p[i0]) i0 = o;
        int i1 = (i0 == 0) ? 1 : 0;
#pragma unroll
        for (int o = 0; o < NDq; o++) if (o != i1 && o != i0 && p[o] > p[i1]) i1 = o;

        int last = inputs[b * Sq + (Sq - 1)];
        int lbl = ldm[(long long)(last - 1) * NEq + goal[b]];
        g_rowloss[b] = p[lbl] - lse2;
        g_rowcorrect[b] = (i0 == lbl || i1 == lbl) ? 1 : 0;
        sidx[0] = i0; sidx[1] = i1;
        slast = last;
    }
    __syncthreads();

    int i0 = sidx[0], i1 = sidx[1], last = slast;
    for (int q = threadIdx.x; q < EDq; q += 64) {
        float v = link_emb[(long long)last * EDq + q];
        if (q < DDq)
            v += 0.5f * (dir_emb[(i0 + 1) * DDq + q] + dir_emb[(i1 + 1) * DDq + q]);
        g_query[b * EDq + q] = v;
    }
}

// ---------------- finalize: loss, direction_correct, pred_d_rand copy ----------------
__global__ void finalize_kernel(const float* __restrict__ pred_d_rand,
                                float* __restrict__ out)
{
    __shared__ float sl[Bq];
    __shared__ int sc[Bq];
    int t = threadIdx.x;
    sl[t] = g_rowloss[t];
    sc[t] = g_rowcorrect[t];
    __syncthreads();
    for (int s = 256; s > 0; s >>= 1) {
        if (t < s) { sl[t] += sl[t + s]; sc[t] += sc[t + s]; }
        __syncthreads();
    }
    const long long PH = (long long)Bq * NEq * PLq;
    if (t == 0) {
        out[PH + Bq * NDq * PLq + 0] = -(sl[0] / (float)Bq) * 5.0f;
        out[PH + Bq * NDq * PLq + 1] = (float)sc[0];
    }
    for (int i = t; i < Bq * NDq * PLq; i += Bq)
        out[PH + i] = pred_d_rand[i];
}

// ---------------- launch ----------------
extern "C" void kernel_launch(void* const* d_in, const int* in_sizes, int n_in,
                              void* d_out, int out_size)
{
    const int*   inputs     = (const int*)d_in[0];
    const int*   directions = (const int*)d_in[1];
    const int*   goal       = (const int*)d_in[2];
    const int*   ldm        = (const int*)d_in[3];
    const float* pred_d_rand= (const float*)d_in[4];
    const float* link_emb   = (const float*)d_in[5];
    const float* dir_emb    = (const float*)d_in[6];
    const float* w_ih       = (const float*)d_in[7];
    const float* b_ih       = (const float*)d_in[8];
    const float* w_hh       = (const float*)d_in[9];
    const float* b_hh       = (const float*)d_in[10];
    const float* W1         = (const float*)d_in[11];
    const float* b1         = (const float*)d_in[12];
    const float* W2         = (const float*)d_in[13];
    const float* b2         = (const float*)d_in[14];
    const float* W3         = (const float*)d_in[15];
    const float* b3         = (const float*)d_in[16];
    float* out = (float*)d_out;

    cudaFuncSetAttribute(lstm_persist_kernel,
                         cudaFuncAttributeMaxDynamicSharedMemorySize, LS_TOTAL);
    cudaFuncSetAttribute(mma_gemm128_kernel,
                         cudaFuncAttributeMaxDynamicSharedMemorySize, GK_TOTAL);

    float *p_linkproj, *p_hfinal, *p_z1, *p_z2, *p_query;
    cudaGetSymbolAddress((void**)&p_linkproj, g_linkproj);
    cudaGetSymbolAddress((void**)&p_hfinal, g_hfinal);
    cudaGetSymbolAddress((void**)&p_z1, g_z1);
    cudaGetSymbolAddress((void**)&p_z2, g_z2);
    cudaGetSymbolAddress((void**)&p_query, g_query);

    // zero h0, c, flags
    init_kernel<<<(Bq * HHq + 255) / 256, 256>>>();

    // link projection (tensor): [8193 x 2048] = link_emb[8193x128] @ w_ih[:, :128]^T
    mma_gemm128_kernel<<<dim3((NEq + 1 + 127) / 128, G4q / 64), 256, GK_TOTAL>>>(
        link_emb, EDq, w_ih, EDq + DDq, nullptr, p_linkproj, G4q, NEq + 1, EDq, 0, 1, 0);

    // dir projection (+ b_ih + b_hh)
    dirproj_kernel<<<((NDq + 1) * G4q + 255) / 256, 256>>>(dir_emb, w_ih, b_ih, b_hh);

    // persistent warp-MMA LSTM (all 128 steps, fp16 2-term, flag-pipelined)
    lstm_persist_kernel<<<dim3(4, 32), 512, LS_TOTAL>>>(inputs, directions, w_hh);

    // MLP (tensor)
    mma_gemm128_kernel<<<dim3(Bq / 128, HHq / 64), 256, GK_TOTAL>>>(
        p_hfinal, HHq, W1, HHq, b1, p_z1, HHq, Bq, HHq, 1, 1, 0);
    mma_gemm128_kernel<<<dim3(Bq / 128, HHq / 64), 256, GK_TOTAL>>>(
        p_z1, HHq, W2, HHq, b2, p_z2, HHq, Bq, HHq, 1, 1, 0);

    // head
    rowhead_kernel<<<Bq, 64>>>(inputs, goal, ldm, W3, b3, link_emb, dir_emb);

    // loss + direction_correct + pred_d_rand passthrough
    finalize_kernel<<<1, Bq>>>(pred_d_rand, out);

    // sim (tensor): query[512x128] @ link_emb[1:]^T -> replicated x5 into pred_hard
    mma_gemm128_kernel<<<dim3(Bq / 128, NEq / 64), 256, GK_TOTAL>>>(
        p_query, EDq, link_emb + EDq, EDq, nullptr, out, (long long)NEq * PLq, Bq, EDq, 0, PLq, NEq);
}

// round 12
// speedup vs baseline: 1.8751x; 1.8751x over previous
#include <cuda_runtime.h>
#include <cuda_bf16.h>
#include <cuda_fp16.h>
#include <math.h>
#include <stdint.h>

#define Bq   512
#define Sq   128
#define NEq  8192
#define EDq  128
#define DDq  32
#define NDq  8
#define HHq  512
#define PLq  5
#define G4q  2048   // 4*H

// ================= warp-MMA helpers (portable PTX: sm_80+) =================
__device__ __forceinline__ uint32_t smem_u32(const void* p) {
    uint32_t a;
    asm("{ .reg .u64 t; cvta.to.shared.u64 t, %1; cvt.u32.u64 %0, t; }" : "=r"(a) : "l"(p));
    return a;
}

__device__ __forceinline__ void ldsm_x4(uint32_t& r0, uint32_t& r1, uint32_t& r2, uint32_t& r3, uint32_t addr) {
    asm volatile("ldmatrix.sync.aligned.m8n8.x4.shared.b16 {%0,%1,%2,%3}, [%4];"
        : "=r"(r0), "=r"(r1), "=r"(r2), "=r"(r3) : "r"(addr));
}
// bf16 MMA (used by the generic GEMM)
__device__ __forceinline__ void mma16816(float* c, uint32_t a0, uint32_t a1, uint32_t a2, uint32_t a3,
                                         uint32_t b0, uint32_t b1) {
    asm volatile(
        "mma.sync.aligned.m16n8k16.row.col.f32.bf16.bf16.f32 "
        "{%0,%1,%2,%3}, {%4,%5,%6,%7}, {%8,%9}, {%0,%1,%2,%3};"
        : "+f"(c[0]), "+f"(c[1]), "+f"(c[2]), "+f"(c[3])
        : "r"(a0), "r"(a1), "r"(a2), "r"(a3), "r"(b0), "r"(b1));
}
// fp16 MMA (LSTM)
__device__ __forceinline__ void mma16816h(float* c, uint32_t a0, uint32_t a1, uint32_t a2, uint32_t a3,
                                          uint32_t b0, uint32_t b1) {
    asm volatile(
        "mma.sync.aligned.m16n8k16.row.col.f32.f16.f16.f32 "
        "{%0,%1,%2,%3}, {%4,%5,%6,%7}, {%8,%9}, {%0,%1,%2,%3};"
        : "+f"(c[0]), "+f"(c[1]), "+f"(c[2]), "+f"(c[3])
        : "r"(a0), "r"(a1), "r"(a2), "r"(a3), "r"(b0), "r"(b1));
}
__device__ __forceinline__ void cp_async16(uint32_t dst, const void* src) {
    asm volatile("cp.async.cg.shared.global [%0], [%1], 16;" :: "r"(dst), "l"(src) : "memory");
}
#define CP_COMMIT() asm volatile("cp.async.commit_group;" ::: "memory")

// fast transcendentals (ex2/rcp approx: rel err ~2^-22, far below fp16-h noise)
__device__ __forceinline__ float ex2f_(float x) {
    float y; asm("ex2.approx.f32 %0, %1;" : "=f"(y) : "f"(x)); return y;
}
__device__ __forceinline__ float rcpf_(float x) {
    float y; asm("rcp.approx.f32 %0, %1;" : "=f"(y) : "f"(x)); return y;
}
#define LOG2E 1.4426950408889634f
__device__ __forceinline__ float fast_sigmoid(float x) {
    return rcpf_(1.0f + ex2f_(-LOG2E * x));
}
__device__ __forceinline__ float fast_tanh(float x) {
    // tanh(x) = 1 - 2/(e^{2x}+1); ex2 overflow -> rcp(inf)=0 -> 1 (correct saturation)
    return 1.0f - 2.0f * rcpf_(ex2f_(2.0f * LOG2E * x) + 1.0f);
}

// split fp32 -> (hi, lo) bf16 pair packed as bf16x2 words
__device__ __forceinline__ void split_pack(float x, float y,
                                           uint32_t& hi, uint32_t& lo) {
    __nv_bfloat16 hx = __float2bfloat16(x);
    __nv_bfloat16 hy = __float2bfloat16(y);
    __nv_bfloat16 lx = __float2bfloat16(x - __bfloat162float(hx));
    __nv_bfloat16 ly = __float2bfloat16(y - __bfloat162float(hy));
    __nv_bfloat162 h2; h2.x = hx; h2.y = hy;
    __nv_bfloat162 l2; l2.x = lx; l2.y = ly;
    hi = *(uint32_t*)&h2;
    lo = *(uint32_t*)&l2;
}
// split fp32 -> (hi, lo) fp16 pair packed as half2 words
__device__ __forceinline__ void split_pack_h(float x, float y,
                                             uint32_t& hi, uint32_t& lo) {
    __half hx = __float2half(x);
    __half hy = __float2half(y);
    __half lx = __float2half(x - __half2float(hx));
    __half ly = __float2half(y - __half2float(hy));
    __half2 h2; h2.x = hx; h2.y = hy;
    __half2 l2; l2.x = lx; l2.y = ly;
    hi = *(uint32_t*)&h2;
    lo = *(uint32_t*)&l2;
}

// ================= scratch (static device globals) =================
__device__ float g_linkproj[(NEq + 1) * G4q];   // 67 MB
__device__ float g_dirproj[(NDq + 1) * G4q];
__device__ __align__(16) __half g_hh[2][Bq * HHq];  // h (fp16), double buffered
__device__ float g_hfinal[Bq * HHq];
__device__ float g_z1[Bq * HHq];
__device__ float g_z2[Bq * HHq];
__device__ float g_query[Bq * EDq];
__device__ float g_rowloss[Bq];
__device__ int   g_rowcorrect[Bq];
__device__ unsigned g_barrier4[4 * 32];   // one counter per batch group, 128B apart

// ---------------- init: zero h0, barriers ----------------
__global__ void init_kernel() {
    int i = blockIdx.x * blockDim.x + threadIdx.x;
    if (i < 4 * 32) g_barrier4[i] = 0u;
    if (i < Bq * HHq) {
        g_hh[0][i] = __float2half(0.0f);
    }
}

// ---------------- dir projection (+ both biases) ----------------
__global__ void dirproj_kernel(const float* __restrict__ dir_emb,
                               const float* __restrict__ w_ih,
                               const float* __restrict__ b_ih,
                               const float* __restrict__ b_hh)
{
    int i = blockIdx.x * blockDim.x + threadIdx.x;
    if (i >= (NDq + 1) * G4q) return;
    int e = i / G4q;
    int n = i % G4q;
    float s = b_ih[n] + b_hh[n];
#pragma unroll
    for (int k = 0; k < DDq; k++)
        s = fmaf(dir_emb[e * DDq + k], w_ih[n * (EDq + DDq) + EDq + k], s);
    g_dirproj[i] = s;
}

// ================= tensor GEMM, K multiple of 128, 3-term bf16 split =================
// C[M,N] = act(A[M,K] @ W[N,K]^T + bias) ; replicated store (reps, repstride)
// block tile 128x64, 8 warps (4m x 2n), warp tile 32x32
#define GK_AHI 0
#define GK_ALO 34816
#define GK_WHI 69632
#define GK_WLO 87040
#define GK_TOTAL 104448
// row strides: 136 bf16 (272B)

__global__ __launch_bounds__(256, 1) void mma_gemm128_kernel(
    const float* __restrict__ A, int lda,
    const float* __restrict__ W, int ldw,
    const float* __restrict__ bias,
    float* __restrict__ C, long long ldc,
    int M, int K, int relu, int reps, long long repstride)
{
    extern __shared__ char sm[];
    const int tid = threadIdx.x;
    const int lane = tid & 31;
    const int wid = tid >> 5;
    const int moff = (wid >> 1) * 32;
    const int noff = (wid & 1) * 32;
    const int mbase = blockIdx.x * 128;
    const int nbase = blockIdx.y * 64;

    float acc[2][4][4];
#pragma unroll
    for (int mt = 0; mt < 2; mt++)
#pragma unroll
        for (int nt = 0; nt < 4; nt++)
#pragma unroll
            for (int r = 0; r < 4; r++) acc[mt][nt][r] = 0.0f;

    const uint32_t smbase = smem_u32(sm);
    const uint32_t aoff = (moff + (lane & 15)) * 272 + (lane >> 4) * 16;
    const uint32_t boff = (noff + ((lane >> 4) & 1) * 8 + (lane & 7)) * 272 + ((lane >> 3) & 1) * 16;

    for (int kb = 0; kb < K; kb += 128) {
        // load + split A tile [128 x 128]
#pragma unroll
        for (int it = 0; it < 16; it++) {
            int idx = tid + it * 256;       // 0..4095
            int r = idx >> 5, q = idx & 31;
            int gm = mbase + r;
            float4 v = (gm < M) ? *(const float4*)(A + (long long)gm * lda + kb + q * 4)
                                : make_float4(0.f, 0.f, 0.f, 0.f);
            uint32_t h0, l0, h1, l1;
            split_pack(v.x, v.y, h0, l0);
            split_pack(v.z, v.w, h1, l1);
            int byte = r * 272 + q * 8;
            *(uint32_t*)(sm + GK_AHI + byte)     = h0;
            *(uint32_t*)(sm + GK_AHI + byte + 4) = h1;
            *(uint32_t*)(sm + GK_ALO + byte)     = l0;
            *(uint32_t*)(sm + GK_ALO + byte + 4) = l1;
        }
        // load + split W tile [64 x 128]
#pragma unroll
        for (int it = 0; it < 8; it++) {
            int idx = tid + it * 256;       // 0..2047
            int j = idx >> 5, q = idx & 31;
            int gn = nbase + j;
            float4 v = *(const float4*)(W + (long long)gn * ldw + kb + q * 4);
            uint32_t h0, l0, h1, l1;
            split_pack(v.x, v.y, h0, l0);
            split_pack(v.z, v.w, h1, l1);
            int byte = j * 272 + q * 8;
            *(uint32_t*)(sm + GK_WHI + byte)     = h0;
            *(uint32_t*)(sm + GK_WHI + byte + 4) = h1;
            *(uint32_t*)(sm + GK_WLO + byte)     = l0;
            *(uint32_t*)(sm + GK_WLO + byte + 4) = l1;
        }
        __syncthreads();

#pragma unroll
        for (int kk = 0; kk < 8; kk++) {
            uint32_t ah[2][4], al[2][4];
#pragma unroll
            for (int mt = 0; mt < 2; mt++) {
                uint32_t addr = smbase + GK_AHI + aoff + mt * (16 * 272) + kk * 32;
                ldsm_x4(ah[mt][0], ah[mt][1], ah[mt][2], ah[mt][3], addr);
                ldsm_x4(al[mt][0], al[mt][1], al[mt][2], al[mt][3], addr + (GK_ALO - GK_AHI));
            }
            uint32_t bh[4][2], bl[4][2];
#pragma unroll
            for (int p = 0; p < 2; p++) {
                uint32_t addr = smbase + GK_WHI + boff + p * (16 * 272) + kk * 32;
                ldsm_x4(bh[2 * p][0], bh[2 * p][1], bh[2 * p + 1][0], bh[2 * p + 1][1], addr);
                ldsm_x4(bl[2 * p][0], bl[2 * p][1], bl[2 * p + 1][0], bl[2 * p + 1][1], addr + (GK_WLO - GK_WHI));
            }
#pragma unroll
            for (int mt = 0; mt < 2; mt++)
#pragma unroll
                for (int nt = 0; nt < 4; nt++) {
                    mma16816(acc[mt][nt], ah[mt][0], ah[mt][1], ah[mt][2], ah[mt][3], bh[nt][0], bh[nt][1]);
                    mma16816(acc[mt][nt], al[mt][0], al[mt][1], al[mt][2], al[mt][3], bh[nt][0], bh[nt][1]);
                    mma16816(acc[mt][nt], ah[mt][0], ah[mt][1], ah[mt][2], ah[mt][3], bl[nt][0], bl[nt][1]);
                }
        }
        __syncthreads();
    }

    // store
    const int g = lane >> 2, tg = lane & 3;
#pragma unroll
    for (int mt = 0; mt < 2; mt++) {
#pragma unroll
        for (int nt = 0; nt < 4; nt++) {
            int col = nbase + noff + nt * 8 + tg * 2;
            int r0 = mbase + moff + mt * 16 + g;
            int r1 = r0 + 8;
            float v0 = acc[mt][nt][0], v1 = acc[mt][nt][1];
            float v2 = acc[mt][nt][2], v3 = acc[mt][nt][3];
            if (bias) {
                float b0 = bias[col], b1v = bias[col + 1];
                v0 += b0; v1 += b1v; v2 += b0; v3 += b1v;
            }
            if (relu) {
                v0 = fmaxf(v0, 0.f); v1 = fmaxf(v1, 0.f);
                v2 = fmaxf(v2, 0.f); v3 = fmaxf(v3, 0.f);
            }
            for (int rp = 0; rp < reps; rp++) {
                long long base = (long long)rp * repstride;
                if (r0 < M) {
                    C[(long long)r0 * ldc + base + col]     = v0;
                    C[(long long)r0 * ldc + base + col + 1] = v1;
                }
                if (r1 < M) {
                    C[(long long)r1 * ldc + base + col]     = v2;
                    C[(long long)r1 * ldc + base + col + 1] = v3;
                }
            }
        }
    }
}

// ================= persistent warp-MMA LSTM (fp16 2-term) =================
// grid (4, 32): blockIdx.x -> 128 batch rows, blockIdx.y -> 16 hidden dims (64 gate cols)
// 512 threads, 16 warps as 4m x 2n x 2k (warp tile 32x32 over half of each 64-k chunk)
// h quantized to fp16 (single buffer); w_hh as fp16 hi+lo (22-bit); gates = ah*bh + ah*bl
// c state lives in SMEM for the whole kernel (CTA-private; never touches global).
// smem: B_hi[64x520 fp16] | B_lo | A: 3 stages x 16KB (hi only), swizzled 128B rows
//       | c state [2048 fp32]   (A region reused for two fp32 partial-gate regions)
#define LS_BHI   0
#define LS_BLO   66560
#define LS_A     133120
#define LS_GATES 133120
#define LS_GSTR  34816      // bytes per partial-gate region (128 * 68 * 4)
#define LS_C     202752     // 2048 * 4 = 8192 bytes
#define LS_TOTAL 210944

__global__ __launch_bounds__(512, 1) void lstm_persist_kernel(
    const int* __restrict__ inputs,
    const int* __restrict__ directions,
    const float* __restrict__ w_hh)
{
    extern __shared__ char sm[];
    const int tid = threadIdx.x;
    const int lane = tid & 31;
    const int wid = tid >> 5;
    const int moff = (wid >> 2) * 32;          // 4 m groups
    const int noff = ((wid >> 1) & 1) * 32;    // 2 n groups
    const int kslice = wid & 1;                // 2 k slices
    const int bbase = blockIdx.x * 128;
    const int dbase = blockIdx.y * 16;
    unsigned* bar = &g_barrier4[blockIdx.x * 32];
    float* c_sm = (float*)(sm + LS_C);

    // ---- zero c state (persistent in smem) ----
#pragma unroll
    for (int q = 0; q < 4; q++)
        c_sm[tid + 512 * q] = 0.0f;

    // ---- convert w_hh slice into persistent smem (fp16 hi/lo) ----
#pragma unroll
    for (int it = 0; it < 16; it++) {
        int idx = tid + it * 512;       // 0..8191
        int j = idx >> 7;               // gate row 0..63
        int kq = idx & 127;             // float4 index
        int gr = (j >> 4) * HHq + dbase + (j & 15);
        float4 v = *(const float4*)(w_hh + (long long)gr * HHq + kq * 4);
        uint32_t h0, l0, h1, l1;
        split_pack_h(v.x, v.y, h0, l0);
        split_pack_h(v.z, v.w, h1, l1);
        int byte = j * 1040 + kq * 8;
        *(uint32_t*)(sm + LS_BHI + byte)     = h0;
        *(uint32_t*)(sm + LS_BHI + byte + 4) = h1;
        *(uint32_t*)(sm + LS_BLO + byte)     = l0;
        *(uint32_t*)(sm + LS_BLO + byte + 4) = l1;
    }
    __syncthreads();

    const uint32_t smbase = smem_u32(sm);
    const uint32_t boff = (noff + ((lane >> 4) & 1) * 8 + (lane & 7)) * 1040 + ((lane >> 3) & 1) * 16;
    const int g = lane >> 2, tg = lane & 3;
    // A staging: 1024 16B units per chunk, 2 per thread (swizzled rows)
    const int sm0 = tid >> 3, su0 = tid & 7;
    const int sm1 = (tid + 512) >> 3, su1 = (tid + 512) & 7;
    const uint32_t sw0 = sm0 * 128 + (((su0 ^ (sm0 & 7)) & 7) << 4);
    const uint32_t sw1 = sm1 * 128 + (((su1 ^ (sm1 & 7)) & 7) << 4);
    // A ldmatrix swizzled addressing pieces
    const int arow = lane & 15;
    const int aunit = lane >> 4;
    const int axor = lane & 7;

    for (int t = 0; t < Sq; t++) {
        const __half* __restrict__ hh = g_hh[t & 1];

        // ---- prologue: issue chunks 0,1 (3 buffers, prefetch depth 2) ----
#pragma unroll
        for (int pc = 0; pc < 2; pc++) {
            uint32_t hi_off = LS_A + (uint32_t)(pc % 3) * 16384u;
            cp_async16(smbase + hi_off + sw0, hh + (long long)(bbase + sm0) * HHq + pc * 64 + su0 * 8);
            cp_async16(smbase + hi_off + sw1, hh + (long long)(bbase + sm1) * HHq + pc * 64 + su1 * 8);
            CP_COMMIT();
        }

        // ---- init accumulators: kslice 0 from linkproj+dirproj, kslice 1 zero ----
        float acc[2][4][4];
        if (kslice == 0) {
#pragma unroll
            for (int mt = 0; mt < 2; mt++) {
#pragma unroll
                for (int ph = 0; ph < 2; ph++) {
                    int row = moff + mt * 16 + g + ph * 8;
                    int b = bbase + row;
                    int L  = inputs[b * Sq + t];
                    int Dp = directions[b * Sq + t];
                    const float* lrow = g_linkproj + (long long)L * G4q;
                    const float* drow = g_dirproj + Dp * G4q;
#pragma unroll
                    for (int nt = 0; nt < 4; nt++) {
                        int j = noff + nt * 8 + tg * 2;
                        int gidx = (j >> 4) * HHq + dbase + (j & 15);
                        float2 lv = *(const float2*)(lrow + gidx);
                        float2 dv = *(const float2*)(drow + gidx);
                        acc[mt][nt][ph * 2 + 0] = lv.x + dv.x;
                        acc[mt][nt][ph * 2 + 1] = lv.y + dv.y;
                    }
                }
            }
        } else {
#pragma unroll
            for (int mt = 0; mt < 2; mt++)
#pragma unroll
                for (int nt = 0; nt < 4; nt++)
#pragma unroll
                    for (int r = 0; r < 4; r++) acc[mt][nt][r] = 0.0f;
        }

        for (int c = 0; c < 8; c++) {
            if (c < 7) asm volatile("cp.async.wait_group 1;" ::: "memory");
            else       asm volatile("cp.async.wait_group 0;" ::: "memory");
            __syncthreads();

            // issue chunk c+2 into buffer (c+2)%3 (last read at chunk c-1, fenced by the sync above)
            if (c + 2 < 8) {
                int nc = c + 2;
                uint32_t hi_off = LS_A + (uint32_t)(nc % 3) * 16384u;
                cp_async16(smbase + hi_off + sw0, hh + (long long)(bbase + sm0) * HHq + nc * 64 + su0 * 8);
                cp_async16(smbase + hi_off + sw1, hh + (long long)(bbase + sm1) * HHq + nc * 64 + su1 * 8);
                CP_COMMIT();
            }

            const uint32_t a_hi = LS_A + (uint32_t)(c % 3) * 16384u;
            const uint32_t b_addr0 = smbase + LS_BHI + boff + c * 128;

            // this warp's half of the 4 k16 slices in this chunk
#pragma unroll
            for (int kk2 = 0; kk2 < 2; kk2++) {
                const int kk = kslice * 2 + kk2;
                uint32_t ah[2][4];
#pragma unroll
                for (int mt = 0; mt < 2; mt++) {
                    uint32_t addr = smbase + a_hi
                        + (uint32_t)(moff + mt * 16 + arow) * 128u
                        + (uint32_t)(((kk * 2 + aunit) ^ axor) << 4);
                    ldsm_x4(ah[mt][0], ah[mt][1], ah[mt][2], ah[mt][3], addr);
                }
#pragma unroll
                for (int p = 0; p < 2; p++) {
                    uint32_t bh2[2][2], bl2[2][2];
                    uint32_t addr = b_addr0 + p * (16 * 1040) + kk * 32;
                    ldsm_x4(bh2[0][0], bh2[0][1], bh2[1][0], bh2[1][1], addr);
                    ldsm_x4(bl2[0][0], bl2[0][1], bl2[1][0], bl2[1][1], addr + (LS_BLO - LS_BHI));
#pragma unroll
                    for (int mt = 0; mt < 2; mt++)
#pragma unroll
                        for (int nl = 0; nl < 2; nl++) {
                            float* a = acc[mt][p * 2 + nl];
                            mma16816h(a, ah[mt][0], ah[mt][1], ah[mt][2], ah[mt][3], bh2[nl][0], bh2[nl][1]);
                            mma16816h(a, ah[mt][0], ah[mt][1], ah[mt][2], ah[mt][3], bl2[nl][0], bl2[nl][1]);
                        }
                }
            }
        }
        __syncthreads();   // all MMA reads of A buffers done before gate-region overwrite

        // ---- stage partial gates into smem: region per kslice ----
        float* gsm = (float*)(sm + LS_GATES + kslice * LS_GSTR);
#pragma unroll
        for (int mt = 0; mt < 2; mt++)
#pragma unroll
            for (int nt = 0; nt < 4; nt++) {
                int row = moff + mt * 16 + g;
                int col = noff + nt * 8 + tg * 2;
                gsm[row * 68 + col]           = acc[mt][nt][0];
                gsm[row * 68 + col + 1]       = acc[mt][nt][1];
                gsm[(row + 8) * 68 + col]     = acc[mt][nt][2];
                gsm[(row + 8) * 68 + col + 1] = acc[mt][nt][3];
            }
        __syncthreads();

        // ---- elementwise LSTM update (2048 cells / 512 threads); c in smem ----
        float* g0 = (float*)(sm + LS_GATES);
        float* g1 = (float*)(sm + LS_GATES + LS_GSTR);
        __half* __restrict__ hho = g_hh[(t + 1) & 1];
#pragma unroll
        for (int q = 0; q < 4; q++) {
            int p = tid + 512 * q;          // 0..2047
            int m = p >> 4, dd = p & 15;
            int b = bbase + m;
            int gi = dbase + dd;
            float iv = g0[m * 68 + dd]      + g1[m * 68 + dd];
            float fv = g0[m * 68 + 16 + dd] + g1[m * 68 + 16 + dd];
            float gv = g0[m * 68 + 32 + dd] + g1[m * 68 + 32 + dd];
            float ov = g0[m * 68 + 48 + dd] + g1[m * 68 + 48 + dd];
            float cc = c_sm[p];
            float cn = fast_sigmoid(fv) * cc + fast_sigmoid(iv) * fast_tanh(gv);
            c_sm[p] = cn;
            float hv = fast_sigmoid(ov) * fast_tanh(cn);
            long long ci = (long long)b * HHq + gi;
            hho[ci] = __float2half(hv);
            if (t == Sq - 1) g_hfinal[ci] = hv;
        }

        // ---- per-batch-group barrier (32 CTAs sharing blockIdx.x) ----
        if (t < Sq - 1) {
            __threadfence();
            __syncthreads();
            if (tid == 0) {
                atomicAdd(bar, 1u);
                unsigned target = 32u * (unsigned)(t + 1);
                while (*((volatile unsigned*)bar) < target) __nanosleep(32);
            }
            __syncthreads();
        }
    }
}

// ---------------- per-row head: logits, log-softmax x2, top-2, label, query ----------------
__global__ void rowhead_kernel(const int* __restrict__ inputs,
                               const int* __restrict__ goal,
                               const int* __restrict__ ldm,
                               const float* __restrict__ W3,
                               const float* __restrict__ b3,
                               const float* __restrict__ link_emb,
                               const float* __restrict__ dir_emb)
{
    int b = blockIdx.x;
    __shared__ float zrow[HHq];
    __shared__ float red[NDq][64];
    __shared__ float lg[NDq];
    __shared__ int sidx[2];
    __shared__ int slast;

    const float* z = g_z2 + b * HHq;
    for (int i = threadIdx.x; i < HHq; i += 64) zrow[i] = z[i];
    __syncthreads();

    float part[NDq];
#pragma unroll
    for (int o = 0; o < NDq; o++) part[o] = 0.0f;
    for (int k = threadIdx.x; k < HHq; k += 64) {
        float zv = zrow[k];
#pragma unroll
        for (int o = 0; o < NDq; o++) part[o] = fmaf(zv, W3[o * HHq + k], part[o]);
    }
#pragma unroll
    for (int o = 0; o < NDq; o++) red[o][threadIdx.x] = part[o];
    __syncthreads();

    if (threadIdx.x < NDq) {
        int o = threadIdx.x;
        float s = 0.0f;
        for (int i = 0; i < 64; i++) s += red[o][i];
        lg[o] = s + b3[o];
    }
    __syncthreads();

    if (threadIdx.x == 0) {
        float mx = lg[0];
#pragma unroll
        for (int o = 1; o < NDq; o++) mx = fmaxf(mx, lg[o]);
        float se = 0.0f;
#pragma unroll
        for (int o = 0; o < NDq; o++) se += expf(lg[o] - mx);
        float lse = mx + logf(se);
        float p[NDq];
#pragma unroll
        for (int o = 0; o < NDq; o++) p[o] = lg[o] - lse;
        float mx2 = p[0];
#pragma unroll
        for (int o = 1; o < NDq; o++) mx2 = fmaxf(mx2, p[o]);
        float se2 = 0.0f;
#pragma unroll
        for (int o = 0; o < NDq; o++) se2 += expf(p[o] - mx2);
        float lse2 = mx2 + logf(se2);
        int i0 = 0;
#pragma unroll
        for (int o = 1; o < NDq; o++) if (p[o] > p[i0]) i0 = o;
        int i1 = (i0 == 0) ? 1 : 0;
#pragma unroll
        for (int o = 0; o < NDq; o++) if (o != i1 && o != i0 && p[o] > p[i1]) i1 = o;

        int last = inputs[b * Sq + (Sq - 1)];
        int lbl = ldm[(long long)(last - 1) * NEq + goal[b]];
        g_rowloss[b] = p[lbl] - lse2;
        g_rowcorrect[b] = (i0 == lbl || i1 == lbl) ? 1 : 0;
        sidx[0] = i0; sidx[1] = i1;
        slast = last;
    }
    __syncthreads();

    int i0 = sidx[0], i1 = sidx[1], last = slast;
    for (int q = threadIdx.x; q < EDq; q += 64) {
        float v = link_emb[(long long)last * EDq + q];
        if (q < DDq)
            v += 0.5f * (dir_emb[(i0 + 1) * DDq + q] + dir_emb[(i1 + 1) * DDq + q]);
        g_query[b * EDq + q] = v;
    }
}

// ---------------- finalize: loss, direction_correct, pred_d_rand copy ----------------
__global__ void finalize_kernel(const float* __restrict__ pred_d_rand,
                                float* __restrict__ out)
{
    __shared__ float sl[Bq];
    __shared__ int sc[Bq];
    int t = threadIdx.x;
    sl[t] = g_rowloss[t];
    sc[t] = g_rowcorrect[t];
    __syncthreads();
    for (int s = 256; s > 0; s >>= 1) {
        if (t < s) { sl[t] += sl[t + s]; sc[t] += sc[t + s]; }
        __syncthreads();
    }
    const long long PH = (long long)Bq * NEq * PLq;
    if (t == 0) {
        out[PH + Bq * NDq * PLq + 0] = -(sl[0] / (float)Bq) * 5.0f;
        out[PH + Bq * NDq * PLq + 1] = (float)sc[0];
    }
    for (int i = t; i < Bq * NDq * PLq; i += Bq)
        out[PH + i] = pred_d_rand[i];
}

// ---------------- launch ----------------
extern "C" void kernel_launch(void* const* d_in, const int* in_sizes, int n_in,
                              void* d_out, int out_size)
{
    const int*   inputs     = (const int*)d_in[0];
    const int*   directions = (const int*)d_in[1];
    const int*   goal       = (const int*)d_in[2];
    const int*   ldm        = (const int*)d_in[3];
    const float* pred_d_rand= (const float*)d_in[4];
    const float* link_emb   = (const float*)d_in[5];
    const float* dir_emb    = (const float*)d_in[6];
    const float* w_ih       = (const float*)d_in[7];
    const float* b_ih       = (const float*)d_in[8];
    const float* w_hh       = (const float*)d_in[9];
    const float* b_hh       = (const float*)d_in[10];
    const float* W1         = (const float*)d_in[11];
    const float* b1         = (const float*)d_in[12];
    const float* W2         = (const float*)d_in[13];
    const float* b2         = (const float*)d_in[14];
    const float* W3         = (const float*)d_in[15];
    const float* b3         = (const float*)d_in[16];
    float* out = (float*)d_out;

    cudaFuncSetAttribute(lstm_persist_kernel,
                         cudaFuncAttributeMaxDynamicSharedMemorySize, LS_TOTAL);
    cudaFuncSetAttribute(mma_gemm128_kernel,
                         cudaFuncAttributeMaxDynamicSharedMemorySize, GK_TOTAL);

    float *p_linkproj, *p_hfinal, *p_z1, *p_z2, *p_query;
    cudaGetSymbolAddress((void**)&p_linkproj, g_linkproj);
    cudaGetSymbolAddress((void**)&p_hfinal, g_hfinal);
    cudaGetSymbolAddress((void**)&p_z1, g_z1);
    cudaGetSymbolAddress((void**)&p_z2, g_z2);
    cudaGetSymbolAddress((void**)&p_query, g_query);

    // zero h0, barriers
    init_kernel<<<(Bq * HHq + 255) / 256, 256>>>();

    // link projection (tensor): [8193 x 2048] = link_emb[8193x128] @ w_ih[:, :128]^T
    mma_gemm128_kernel<<<dim3((NEq + 1 + 127) / 128, G4q / 64), 256, GK_TOTAL>>>(
        link_emb, EDq, w_ih, EDq + DDq, nullptr, p_linkproj, G4q, NEq + 1, EDq, 0, 1, 0);

    // dir projection (+ b_ih + b_hh)
    dirproj_kernel<<<((NDq + 1) * G4q + 255) / 256, 256>>>(dir_emb, w_ih, b_ih, b_hh);

    // persistent warp-MMA LSTM (all 128 steps, fp16 2-term, c in smem, fast math)
    lstm_persist_kernel<<<dim3(4, 32), 512, LS_TOTAL>>>(inputs, directions, w_hh);

    // MLP (tensor)
    mma_gemm128_kernel<<<dim3(Bq / 128, HHq / 64), 256, GK_TOTAL>>>(
        p_hfinal, HHq, W1, HHq, b1, p_z1, HHq, Bq, HHq, 1, 1, 0);
    mma_gemm128_kernel<<<dim3(Bq / 128, HHq / 64), 256, GK_TOTAL>>>(
        p_z1, HHq, W2, HHq, b2, p_z2, HHq, Bq, HHq, 1, 1, 0);

    // head
    rowhead_kernel<<<Bq, 64>>>(inputs, goal, ldm, W3, b3, link_emb, dir_emb);

    // loss + direction_correct + pred_d_rand passthrough
    finalize_kernel<<<1, Bq>>>(pred_d_rand, out);

    // sim (tensor): query[512x128] @ link_emb[1:]^T -> replicated x5 into pred_hard
    mma_gemm128_kernel<<<dim3(Bq / 128, NEq / 64), 256, GK_TOTAL>>>(
        p_query, EDq, link_emb + EDq, EDq, nullptr, out, (long long)NEq * PLq, Bq, EDq, 0, PLq, NEq);
}

// round 13
// speedup vs baseline: 1.8806x; 1.0029x over previous
#include <cuda_runtime.h>
#include <cuda_bf16.h>
#include <cuda_fp16.h>
#include <math.h>
#include <stdint.h>

#define Bq   512
#define Sq   128
#define NEq  8192
#define EDq  128
#define DDq  32
#define NDq  8
#define HHq  512
#define PLq  5
#define G4q  2048   // 4*H

// ================= warp-MMA helpers (portable PTX: sm_80+) =================
__device__ __forceinline__ uint32_t smem_u32(const void* p) {
    uint32_t a;
    asm("{ .reg .u64 t; cvta.to.shared.u64 t, %1; cvt.u32.u64 %0, t; }" : "=r"(a) : "l"(p));
    return a;
}

__device__ __forceinline__ void ldsm_x4(uint32_t& r0, uint32_t& r1, uint32_t& r2, uint32_t& r3, uint32_t addr) {
    asm volatile("ldmatrix.sync.aligned.m8n8.x4.shared.b16 {%0,%1,%2,%3}, [%4];"
        : "=r"(r0), "=r"(r1), "=r"(r2), "=r"(r3) : "r"(addr));
}
// bf16 MMA (used by the generic GEMM)
__device__ __forceinline__ void mma16816(float* c, uint32_t a0, uint32_t a1, uint32_t a2, uint32_t a3,
                                         uint32_t b0, uint32_t b1) {
    asm volatile(
        "mma.sync.aligned.m16n8k16.row.col.f32.bf16.bf16.f32 "
        "{%0,%1,%2,%3}, {%4,%5,%6,%7}, {%8,%9}, {%0,%1,%2,%3};"
        : "+f"(c[0]), "+f"(c[1]), "+f"(c[2]), "+f"(c[3])
        : "r"(a0), "r"(a1), "r"(a2), "r"(a3), "r"(b0), "r"(b1));
}
// fp16 MMA (LSTM)
__device__ __forceinline__ void mma16816h(float* c, uint32_t a0, uint32_t a1, uint32_t a2, uint32_t a3,
                                          uint32_t b0, uint32_t b1) {
    asm volatile(
        "mma.sync.aligned.m16n8k16.row.col.f32.f16.f16.f32 "
        "{%0,%1,%2,%3}, {%4,%5,%6,%7}, {%8,%9}, {%0,%1,%2,%3};"
        : "+f"(c[0]), "+f"(c[1]), "+f"(c[2]), "+f"(c[3])
        : "r"(a0), "r"(a1), "r"(a2), "r"(a3), "r"(b0), "r"(b1));
}
__device__ __forceinline__ void cp_async16(uint32_t dst, const void* src) {
    asm volatile("cp.async.cg.shared.global [%0], [%1], 16;" :: "r"(dst), "l"(src) : "memory");
}
#define CP_COMMIT() asm volatile("cp.async.commit_group;" ::: "memory")

// fast transcendentals (ex2/rcp approx: rel err ~2^-22, far below fp16-h noise)
__device__ __forceinline__ float ex2f_(float x) {
    float y; asm("ex2.approx.f32 %0, %1;" : "=f"(y) : "f"(x)); return y;
}
__device__ __forceinline__ float rcpf_(float x) {
    float y; asm("rcp.approx.f32 %0, %1;" : "=f"(y) : "f"(x)); return y;
}
#define LOG2E 1.4426950408889634f
__device__ __forceinline__ float fast_sigmoid(float x) {
    return rcpf_(1.0f + ex2f_(-LOG2E * x));
}
__device__ __forceinline__ float fast_tanh(float x) {
    // tanh(x) = 1 - 2/(e^{2x}+1); ex2 overflow -> rcp(inf)=0 -> 1 (correct saturation)
    return 1.0f - 2.0f * rcpf_(ex2f_(2.0f * LOG2E * x) + 1.0f);
}

// split fp32 -> (hi, lo) bf16 pair packed as bf16x2 words
__device__ __forceinline__ void split_pack(float x, float y,
                                           uint32_t& hi, uint32_t& lo) {
    __nv_bfloat16 hx = __float2bfloat16(x);
    __nv_bfloat16 hy = __float2bfloat16(y);
    __nv_bfloat16 lx = __float2bfloat16(x - __bfloat162float(hx));
    __nv_bfloat16 ly = __float2bfloat16(y - __bfloat162float(hy));
    __nv_bfloat162 h2; h2.x = hx; h2.y = hy;
    __nv_bfloat162 l2; l2.x = lx; l2.y = ly;
    hi = *(uint32_t*)&h2;
    lo = *(uint32_t*)&l2;
}
// split fp32 -> (hi, lo) fp16 pair packed as half2 words
__device__ __forceinline__ void split_pack_h(float x, float y,
                                             uint32_t& hi, uint32_t& lo) {
    __half hx = __float2half(x);
    __half hy = __float2half(y);
    __half lx = __float2half(x - __half2float(hx));
    __half ly = __float2half(y - __half2float(hy));
    __half2 h2; h2.x = hx; h2.y = hy;
    __half2 l2; l2.x = lx; l2.y = ly;
    hi = *(uint32_t*)&h2;
    lo = *(uint32_t*)&l2;
}

// ================= scratch (static device globals) =================
__device__ float g_linkproj[(NEq + 1) * G4q];   // 67 MB
__device__ float g_dirproj[(NDq + 1) * G4q];
__device__ __align__(16) __half g_hh[2][Bq * HHq];  // h (fp16), double buffered
__device__ float g_hfinal[Bq * HHq];
__device__ float g_z1[Bq * HHq];
__device__ float g_z2[Bq * HHq];
__device__ float g_query[Bq * EDq];
__device__ float g_rowloss[Bq];
__device__ int   g_rowcorrect[Bq];
__device__ unsigned g_barrier4[4 * 32];   // one counter per batch group, 128B apart

// ---------------- init: zero h0, barriers ----------------
__global__ void init_kernel() {
    int i = blockIdx.x * blockDim.x + threadIdx.x;
    if (i < 4 * 32) g_barrier4[i] = 0u;
    if (i < Bq * HHq) {
        g_hh[0][i] = __float2half(0.0f);
    }
}

// ---------------- dir projection (+ both biases) ----------------
__global__ void dirproj_kernel(const float* __restrict__ dir_emb,
                               const float* __restrict__ w_ih,
                               const float* __restrict__ b_ih,
                               const float* __restrict__ b_hh)
{
    int i = blockIdx.x * blockDim.x + threadIdx.x;
    if (i >= (NDq + 1) * G4q) return;
    int e = i / G4q;
    int n = i % G4q;
    float s = b_ih[n] + b_hh[n];
#pragma unroll
    for (int k = 0; k < DDq; k++)
        s = fmaf(dir_emb[e * DDq + k], w_ih[n * (EDq + DDq) + EDq + k], s);
    g_dirproj[i] = s;
}

// ================= tensor GEMM, K multiple of 128, 3-term bf16 split =================
// C[M,N] = act(A[M,K] @ W[N,K]^T + bias) ; replicated store (reps, repstride)
// block tile 128x64, 8 warps (4m x 2n), warp tile 32x32
#define GK_AHI 0
#define GK_ALO 34816
#define GK_WHI 69632
#define GK_WLO 87040
#define GK_TOTAL 104448
// row strides: 136 bf16 (272B)

__global__ __launch_bounds__(256, 1) void mma_gemm128_kernel(
    const float* __restrict__ A, int lda,
    const float* __restrict__ W, int ldw,
    const float* __restrict__ bias,
    float* __restrict__ C, long long ldc,
    int M, int K, int relu, int reps, long long repstride)
{
    extern __shared__ char sm[];
    const int tid = threadIdx.x;
    const int lane = tid & 31;
    const int wid = tid >> 5;
    const int moff = (wid >> 1) * 32;
    const int noff = (wid & 1) * 32;
    const int mbase = blockIdx.x * 128;
    const int nbase = blockIdx.y * 64;

    float acc[2][4][4];
#pragma unroll
    for (int mt = 0; mt < 2; mt++)
#pragma unroll
        for (int nt = 0; nt < 4; nt++)
#pragma unroll
            for (int r = 0; r < 4; r++) acc[mt][nt][r] = 0.0f;

    const uint32_t smbase = smem_u32(sm);
    const uint32_t aoff = (moff + (lane & 15)) * 272 + (lane >> 4) * 16;
    const uint32_t boff = (noff + ((lane >> 4) & 1) * 8 + (lane & 7)) * 272 + ((lane >> 3) & 1) * 16;

    for (int kb = 0; kb < K; kb += 128) {
        // load + split A tile [128 x 128]
#pragma unroll
        for (int it = 0; it < 16; it++) {
            int idx = tid + it * 256;       // 0..4095
            int r = idx >> 5, q = idx & 31;
            int gm = mbase + r;
            float4 v = (gm < M) ? *(const float4*)(A + (long long)gm * lda + kb + q * 4)
                                : make_float4(0.f, 0.f, 0.f, 0.f);
            uint32_t h0, l0, h1, l1;
            split_pack(v.x, v.y, h0, l0);
            split_pack(v.z, v.w, h1, l1);
            int byte = r * 272 + q * 8;
            *(uint32_t*)(sm + GK_AHI + byte)     = h0;
            *(uint32_t*)(sm + GK_AHI + byte + 4) = h1;
            *(uint32_t*)(sm + GK_ALO + byte)     = l0;
            *(uint32_t*)(sm + GK_ALO + byte + 4) = l1;
        }
        // load + split W tile [64 x 128]
#pragma unroll
        for (int it = 0; it < 8; it++) {
            int idx = tid + it * 256;       // 0..2047
            int j = idx >> 5, q = idx & 31;
            int gn = nbase + j;
            float4 v = *(const float4*)(W + (long long)gn * ldw + kb + q * 4);
            uint32_t h0, l0, h1, l1;
            split_pack(v.x, v.y, h0, l0);
            split_pack(v.z, v.w, h1, l1);
            int byte = j * 272 + q * 8;
            *(uint32_t*)(sm + GK_WHI + byte)     = h0;
            *(uint32_t*)(sm + GK_WHI + byte + 4) = h1;
            *(uint32_t*)(sm + GK_WLO + byte)     = l0;
            *(uint32_t*)(sm + GK_WLO + byte + 4) = l1;
        }
        __syncthreads();

#pragma unroll
        for (int kk = 0; kk < 8; kk++) {
            uint32_t ah[2][4], al[2][4];
#pragma unroll
            for (int mt = 0; mt < 2; mt++) {
                uint32_t addr = smbase + GK_AHI + aoff + mt * (16 * 272) + kk * 32;
                ldsm_x4(ah[mt][0], ah[mt][1], ah[mt][2], ah[mt][3], addr);
                ldsm_x4(al[mt][0], al[mt][1], al[mt][2], al[mt][3], addr + (GK_ALO - GK_AHI));
            }
            uint32_t bh[4][2], bl[4][2];
#pragma unroll
            for (int p = 0; p < 2; p++) {
                uint32_t addr = smbase + GK_WHI + boff + p * (16 * 272) + kk * 32;
                ldsm_x4(bh[2 * p][0], bh[2 * p][1], bh[2 * p + 1][0], bh[2 * p + 1][1], addr);
                ldsm_x4(bl[2 * p][0], bl[2 * p][1], bl[2 * p + 1][0], bl[2 * p + 1][1], addr + (GK_WLO - GK_WHI));
            }
#pragma unroll
            for (int mt = 0; mt < 2; mt++)
#pragma unroll
                for (int nt = 0; nt < 4; nt++) {
                    mma16816(acc[mt][nt], ah[mt][0], ah[mt][1], ah[mt][2], ah[mt][3], bh[nt][0], bh[nt][1]);
                    mma16816(acc[mt][nt], al[mt][0], al[mt][1], al[mt][2], al[mt][3], bh[nt][0], bh[nt][1]);
                    mma16816(acc[mt][nt], ah[mt][0], ah[mt][1], ah[mt][2], ah[mt][3], bl[nt][0], bl[nt][1]);
                }
        }
        __syncthreads();
    }

    // store
    const int g = lane >> 2, tg = lane & 3;
#pragma unroll
    for (int mt = 0; mt < 2; mt++) {
#pragma unroll
        for (int nt = 0; nt < 4; nt++) {
            int col = nbase + noff + nt * 8 + tg * 2;
            int r0 = mbase + moff + mt * 16 + g;
            int r1 = r0 + 8;
            float v0 = acc[mt][nt][0], v1 = acc[mt][nt][1];
            float v2 = acc[mt][nt][2], v3 = acc[mt][nt][3];
            if (bias) {
                float b0 = bias[col], b1v = bias[col + 1];
                v0 += b0; v1 += b1v; v2 += b0; v3 += b1v;
            }
            if (relu) {
                v0 = fmaxf(v0, 0.f); v1 = fmaxf(v1, 0.f);
                v2 = fmaxf(v2, 0.f); v3 = fmaxf(v3, 0.f);
            }
            for (int rp = 0; rp < reps; rp++) {
                long long base = (long long)rp * repstride;
                if (r0 < M) {
                    C[(long long)r0 * ldc + base + col]     = v0;
                    C[(long long)r0 * ldc + base + col + 1] = v1;
                }
                if (r1 < M) {
                    C[(long long)r1 * ldc + base + col]     = v2;
                    C[(long long)r1 * ldc + base + col + 1] = v3;
                }
            }
        }
    }
}

// ================= persistent warp-MMA LSTM (fp16 2-term, 128-k chunks) =================
// grid (4, 32): blockIdx.x -> 128 batch rows, blockIdx.y -> 16 hidden dims (64 gate cols)
// 512 threads, 16 warps as 4m x 2n x 2k (each warp: 4 of the 8 k16 slices per 128-k chunk)
// 4 chunks of 128 k per step, 2 A stages (depth-1 prefetch) -> half the syncs of 64-k/3-stage.
// A stage 32KB, 256B rows, swizzle: phys_unit = (u&8) | ((u&7)^(row&7)).
// smem: B_hi[64x520 fp16] | B_lo | A: 2 stages x 32KB | (gates overlay A) | c state
#define LS_BHI   0
#define LS_BLO   66560
#define LS_A     133120
#define LS_GATES 133120
#define LS_GSTR  34816      // bytes per partial-gate region (128 * 68 * 4)
#define LS_C     202752     // 2048 * 4 = 8192 bytes
#define LS_TOTAL 210944

__global__ __launch_bounds__(512, 1) void lstm_persist_kernel(
    const int* __restrict__ inputs,
    const int* __restrict__ directions,
    const float* __restrict__ w_hh)
{
    extern __shared__ char sm[];
    const int tid = threadIdx.x;
    const int lane = tid & 31;
    const int wid = tid >> 5;
    const int moff = (wid >> 2) * 32;          // 4 m groups
    const int noff = ((wid >> 1) & 1) * 32;    // 2 n groups
    const int kslice = wid & 1;                // 2 k slices
    const int bbase = blockIdx.x * 128;
    const int dbase = blockIdx.y * 16;
    unsigned* bar = &g_barrier4[blockIdx.x * 32];
    float* c_sm = (float*)(sm + LS_C);

    // ---- zero c state (persistent in smem) ----
#pragma unroll
    for (int q = 0; q < 4; q++)
        c_sm[tid + 512 * q] = 0.0f;

    // ---- convert w_hh slice into persistent smem (fp16 hi/lo) ----
#pragma unroll
    for (int it = 0; it < 16; it++) {
        int idx = tid + it * 512;       // 0..8191
        int j = idx >> 7;               // gate row 0..63
        int kq = idx & 127;             // float4 index
        int gr = (j >> 4) * HHq + dbase + (j & 15);
        float4 v = *(const float4*)(w_hh + (long long)gr * HHq + kq * 4);
        uint32_t h0, l0, h1, l1;
        split_pack_h(v.x, v.y, h0, l0);
        split_pack_h(v.z, v.w, h1, l1);
        int byte = j * 1040 + kq * 8;
        *(uint32_t*)(sm + LS_BHI + byte)     = h0;
        *(uint32_t*)(sm + LS_BHI + byte + 4) = h1;
        *(uint32_t*)(sm + LS_BLO + byte)     = l0;
        *(uint32_t*)(sm + LS_BLO + byte + 4) = l1;
    }
    __syncthreads();

    const uint32_t smbase = smem_u32(sm);
    const uint32_t boff = (noff + ((lane >> 4) & 1) * 8 + (lane & 7)) * 1040 + ((lane >> 3) & 1) * 16;
    const int g = lane >> 2, tg = lane & 3;
    // A staging: 2048 16B units per 128-k chunk, 4 per thread (256B swizzled rows)
    int srow[4], sunit[4]; uint32_t ssw[4];
#pragma unroll
    for (int u = 0; u < 4; u++) {
        int idx = tid + u * 512;            // 0..2047
        srow[u] = idx >> 4;                 // row 0..127
        sunit[u] = idx & 15;                // 16B unit 0..15
        int phys = (sunit[u] & 8) | ((sunit[u] & 7) ^ (srow[u] & 7));
        ssw[u] = (uint32_t)(srow[u] * 256 + phys * 16);
    }
    // A ldmatrix swizzled addressing pieces
    const int arow = lane & 15;
    const int aunit = lane >> 4;
    const int axor = lane & 7;

    for (int t = 0; t < Sq; t++) {
        const __half* __restrict__ hh = g_hh[t & 1];

        // ---- prologue: issue chunk 0 (2 stages, depth-1 prefetch) ----
        {
            uint32_t a_off = LS_A;          // buf 0
#pragma unroll
            for (int u = 0; u < 4; u++)
                cp_async16(smbase + a_off + ssw[u],
                           hh + (long long)(bbase + srow[u]) * HHq + sunit[u] * 8);
            CP_COMMIT();
        }

        // ---- init accumulators: kslice 0 from linkproj+dirproj, kslice 1 zero ----
        float acc[2][4][4];
        if (kslice == 0) {
#pragma unroll
            for (int mt = 0; mt < 2; mt++) {
#pragma unroll
                for (int ph = 0; ph < 2; ph++) {
                    int row = moff + mt * 16 + g + ph * 8;
                    int b = bbase + row;
                    int L  = inputs[b * Sq + t];
                    int Dp = directions[b * Sq + t];
                    const float* lrow = g_linkproj + (long long)L * G4q;
                    const float* drow = g_dirproj + Dp * G4q;
#pragma unroll
                    for (int nt = 0; nt < 4; nt++) {
                        int j = noff + nt * 8 + tg * 2;
                        int gidx = (j >> 4) * HHq + dbase + (j & 15);
                        float2 lv = *(const float2*)(lrow + gidx);
                        float2 dv = *(const float2*)(drow + gidx);
                        acc[mt][nt][ph * 2 + 0] = lv.x + dv.x;
                        acc[mt][nt][ph * 2 + 1] = lv.y + dv.y;
                    }
                }
            }
        } else {
#pragma unroll
            for (int mt = 0; mt < 2; mt++)
#pragma unroll
                for (int nt = 0; nt < 4; nt++)
#pragma unroll
                    for (int r = 0; r < 4; r++) acc[mt][nt][r] = 0.0f;
        }

        for (int c = 0; c < 4; c++) {
            asm volatile("cp.async.wait_group 0;" ::: "memory");
            __syncthreads();

            // issue chunk c+1 into the other buffer (its prior reads done before the sync above)
            if (c + 1 < 4) {
                uint32_t a_off = LS_A + (uint32_t)((c + 1) & 1) * 32768u;
#pragma unroll
                for (int u = 0; u < 4; u++)
                    cp_async16(smbase + a_off + ssw[u],
                               hh + (long long)(bbase + srow[u]) * HHq + (c + 1) * 128 + sunit[u] * 8);
                CP_COMMIT();
            }

            const uint32_t a_base = LS_A + (uint32_t)(c & 1) * 32768u;
            const uint32_t b_addr0 = smbase + LS_BHI + boff + c * 256;

            // this warp's half of the 8 k16 slices in this 128-k chunk
#pragma unroll
            for (int kk2 = 0; kk2 < 4; kk2++) {
                const int kk = kslice * 4 + kk2;
                const int u = kk * 2 + aunit;       // 16B unit within 256B row
                const int physbase = (u & 8);
                uint32_t ah[2][4];
#pragma unroll
                for (int mt = 0; mt < 2; mt++) {
                    int row = moff + mt * 16 + arow;
                    int phys = physbase | ((u & 7) ^ (row & 7));
                    uint32_t addr = smbase + a_base + (uint32_t)(row * 256 + phys * 16);
                    ldsm_x4(ah[mt][0], ah[mt][1], ah[mt][2], ah[mt][3], addr);
                }
#pragma unroll
                for (int p = 0; p < 2; p++) {
                    uint32_t bh2[2][2], bl2[2][2];
                    uint32_t addr = b_addr0 + p * (16 * 1040) + kk * 32;
                    ldsm_x4(bh2[0][0], bh2[0][1], bh2[1][0], bh2[1][1], addr);
                    ldsm_x4(bl2[0][0], bl2[0][1], bl2[1][0], bl2[1][1], addr + (LS_BLO - LS_BHI));
#pragma unroll
                    for (int mt = 0; mt < 2; mt++)
#pragma unroll
                        for (int nl = 0; nl < 2; nl++) {
                            float* a = acc[mt][p * 2 + nl];
                            mma16816h(a, ah[mt][0], ah[mt][1], ah[mt][2], ah[mt][3], bh2[nl][0], bh2[nl][1]);
                            mma16816h(a, ah[mt][0], ah[mt][1], ah[mt][2], ah[mt][3], bl2[nl][0], bl2[nl][1]);
                        }
                }
            }
        }
        __syncthreads();   // all MMA reads of A buffers done before gate-region overwrite

        // ---- stage partial gates into smem: region per kslice ----
        float* gsm = (float*)(sm + LS_GATES + kslice * LS_GSTR);
#pragma unroll
        for (int mt = 0; mt < 2; mt++)
#pragma unroll
            for (int nt = 0; nt < 4; nt++) {
                int row = moff + mt * 16 + g;
                int col = noff + nt * 8 + tg * 2;
                gsm[row * 68 + col]           = acc[mt][nt][0];
                gsm[row * 68 + col + 1]       = acc[mt][nt][1];
                gsm[(row + 8) * 68 + col]     = acc[mt][nt][2];
                gsm[(row + 8) * 68 + col + 1] = acc[mt][nt][3];
            }
        __syncthreads();

        // ---- elementwise LSTM update (2048 cells / 512 threads); c in smem ----
        float* g0 = (float*)(sm + LS_GATES);
        float* g1 = (float*)(sm + LS_GATES + LS_GSTR);
        __half* __restrict__ hho = g_hh[(t + 1) & 1];
#pragma unroll
        for (int q = 0; q < 4; q++) {
            int p = tid + 512 * q;          // 0..2047
            int m = p >> 4, dd = p & 15;
            int b = bbase + m;
            int gi = dbase + dd;
            float iv = g0[m * 68 + dd]      + g1[m * 68 + dd];
            float fv = g0[m * 68 + 16 + dd] + g1[m * 68 + 16 + dd];
            float gv = g0[m * 68 + 32 + dd] + g1[m * 68 + 32 + dd];
            float ov = g0[m * 68 + 48 + dd] + g1[m * 68 + 48 + dd];
            float cc = c_sm[p];
            float cn = fast_sigmoid(fv) * cc + fast_sigmoid(iv) * fast_tanh(gv);
            c_sm[p] = cn;
            float hv = fast_sigmoid(ov) * fast_tanh(cn);
            long long ci = (long long)b * HHq + gi;
            hho[ci] = __float2half(hv);
            if (t == Sq - 1) g_hfinal[ci] = hv;
        }

        // ---- per-batch-group barrier (32 CTAs sharing blockIdx.x) ----
        if (t < Sq - 1) {
            __threadfence();
            __syncthreads();
            if (tid == 0) {
                atomicAdd(bar, 1u);
                unsigned target = 32u * (unsigned)(t + 1);
                while (*((volatile unsigned*)bar) < target) __nanosleep(32);
            }
            __syncthreads();
        }
    }
}

// ---------------- per-row head: logits, log-softmax x2, top-2, label, query ----------------
__global__ void rowhead_kernel(const int* __restrict__ inputs,
                               const int* __restrict__ goal,
                               const int* __restrict__ ldm,
                               const float* __restrict__ W3,
                               const float* __restrict__ b3,
                               const float* __restrict__ link_emb,
                               const float* __restrict__ dir_emb)
{
    int b = blockIdx.x;
    __shared__ float zrow[HHq];
    __shared__ float red[NDq][64];
    __shared__ float lg[NDq];
    __shared__ int sidx[2];
    __shared__ int slast;

    const float* z = g_z2 + b * HHq;
    for (int i = threadIdx.x; i < HHq; i += 64) zrow[i] = z[i];
    __syncthreads();

    float part[NDq];
#pragma unroll
    for (int o = 0; o < NDq; o++) part[o] = 0.0f;
    for (int k = threadIdx.x; k < HHq; k += 64) {
        float zv = zrow[k];
#pragma unroll
        for (int o = 0; o < NDq; o++) part[o] = fmaf(zv, W3[o * HHq + k], part[o]);
    }
#pragma unroll
    for (int o = 0; o < NDq; o++) red[o][threadIdx.x] = part[o];
    __syncthreads();

    if (threadIdx.x < NDq) {
        int o = threadIdx.x;
        float s = 0.0f;
        for (int i = 0; i < 64; i++) s += red[o][i];
        lg[o] = s + b3[o];
    }
    __syncthreads();

    if (threadIdx.x == 0) {
        float mx = lg[0];
#pragma unroll
        for (int o = 1; o < NDq; o++) mx = fmaxf(mx, lg[o]);
        float se = 0.0f;
#pragma unroll
        for (int o = 0; o < NDq; o++) se += expf(lg[o] - mx);
        float lse = mx + logf(se);
        float p[NDq];
#pragma unroll
        for (int o = 0; o < NDq; o++) p[o] = lg[o] - lse;
        float mx2 = p[0];
#pragma unroll
        for (int o = 1; o < NDq; o++) mx2 = fmaxf(mx2, p[o]);
        float se2 = 0.0f;
#pragma unroll
        for (int o = 0; o < NDq; o++) se2 += expf(p[o] - mx2);
        float lse2 = mx2 + logf(se2);
        int i0 = 0;
#pragma unroll
        for (int o = 1; o < NDq; o++) if (p[o] > p[i0]) i0 = o;
        int i1 = (i0 == 0) ? 1 : 0;
#pragma unroll
        for (int o = 0; o < NDq; o++) if (o != i1 && o != i0 && p[o] > p[i1]) i1 = o;

        int last = inputs[b * Sq + (Sq - 1)];
        int lbl = ldm[(long long)(last - 1) * NEq + goal[b]];
        g_rowloss[b] = p[lbl] - lse2;
        g_rowcorrect[b] = (i0 == lbl || i1 == lbl) ? 1 : 0;
        sidx[0] = i0; sidx[1] = i1;
        slast = last;
    }
    __syncthreads();

    int i0 = sidx[0], i1 = sidx[1], last = slast;
    for (int q = threadIdx.x; q < EDq; q += 64) {
        float v = link_emb[(long long)last * EDq + q];
        if (q < DDq)
            v += 0.5f * (dir_emb[(i0 + 1) * DDq + q] + dir_emb[(i1 + 1) * DDq + q]);
        g_query[b * EDq + q] = v;
    }
}

// ---------------- finalize: loss, direction_correct, pred_d_rand copy ----------------
__global__ void finalize_kernel(const float* __restrict__ pred_d_rand,
                                float* __restrict__ out)
{
    __shared__ float sl[Bq];
    __shared__ int sc[Bq];
    int t = threadIdx.x;
    sl[t] = g_rowloss[t];
    sc[t] = g_rowcorrect[t];
    __syncthreads();
    for (int s = 256; s > 0; s >>= 1) {
        if (t < s) { sl[t] += sl[t + s]; sc[t] += sc[t + s]; }
        __syncthreads();
    }
    const long long PH = (long long)Bq * NEq * PLq;
    if (t == 0) {
        out[PH + Bq * NDq * PLq + 0] = -(sl[0] / (float)Bq) * 5.0f;
        out[PH + Bq * NDq * PLq + 1] = (float)sc[0];
    }
    for (int i = t; i < Bq * NDq * PLq; i += Bq)
        out[PH + i] = pred_d_rand[i];
}

// ---------------- launch ----------------
extern "C" void kernel_launch(void* const* d_in, const int* in_sizes, int n_in,
                              void* d_out, int out_size)
{
    const int*   inputs     = (const int*)d_in[0];
    const int*   directions = (const int*)d_in[1];
    const int*   goal       = (const int*)d_in[2];
    const int*   ldm        = (const int*)d_in[3];
    const float* pred_d_rand= (const float*)d_in[4];
    const float* link_emb   = (const float*)d_in[5];
    const float* dir_emb    = (const float*)d_in[6];
    const float* w_ih       = (const float*)d_in[7];
    const float* b_ih       = (const float*)d_in[8];
    const float* w_hh       = (const float*)d_in[9];
    const float* b_hh       = (const float*)d_in[10];
    const float* W1         = (const float*)d_in[11];
    const float* b1         = (const float*)d_in[12];
    const float* W2         = (const float*)d_in[13];
    const float* b2         = (const float*)d_in[14];
    const float* W3         = (const float*)d_in[15];
    const float* b3         = (const float*)d_in[16];
    float* out = (float*)d_out;

    cudaFuncSetAttribute(lstm_persist_kernel,
                         cudaFuncAttributeMaxDynamicSharedMemorySize, LS_TOTAL);
    cudaFuncSetAttribute(mma_gemm128_kernel,
                         cudaFuncAttributeMaxDynamicSharedMemorySize, GK_TOTAL);

    float *p_linkproj, *p_hfinal, *p_z1, *p_z2, *p_query;
    cudaGetSymbolAddress((void**)&p_linkproj, g_linkproj);
    cudaGetSymbolAddress((void**)&p_hfinal, g_hfinal);
    cudaGetSymbolAddress((void**)&p_z1, g_z1);
    cudaGetSymbolAddress((void**)&p_z2, g_z2);
    cudaGetSymbolAddress((void**)&p_query, g_query);

    // zero h0, barriers
    init_kernel<<<(Bq * HHq + 255) / 256, 256>>>();

    // link projection (tensor): [8193 x 2048] = link_emb[8193x128] @ w_ih[:, :128]^T
    mma_gemm128_kernel<<<dim3((NEq + 1 + 127) / 128, G4q / 64), 256, GK_TOTAL>>>(
        link_emb, EDq, w_ih, EDq + DDq, nullptr, p_linkproj, G4q, NEq + 1, EDq, 0, 1, 0);

    // dir projection (+ b_ih + b_hh)
    dirproj_kernel<<<((NDq + 1) * G4q + 255) / 256, 256>>>(dir_emb, w_ih, b_ih, b_hh);

    // persistent warp-MMA LSTM (all 128 steps, fp16 2-term, 128-k chunks, c in smem)
    lstm_persist_kernel<<<dim3(4, 32), 512, LS_TOTAL>>>(inputs, directions, w_hh);

    // MLP (tensor)
    mma_gemm128_kernel<<<dim3(Bq / 128, HHq / 64), 256, GK_TOTAL>>>(
        p_hfinal, HHq, W1, HHq, b1, p_z1, HHq, Bq, HHq, 1, 1, 0);
    mma_gemm128_kernel<<<dim3(Bq / 128, HHq / 64), 256, GK_TOTAL>>>(
        p_z1, HHq, W2, HHq, b2, p_z2, HHq, Bq, HHq, 1, 1, 0);

    // head
    rowhead_kernel<<<Bq, 64>>>(inputs, goal, ldm, W3, b3, link_emb, dir_emb);

    // loss + direction_correct + pred_d_rand passthrough
    finalize_kernel<<<1, Bq>>>(pred_d_rand, out);

    // sim (tensor): query[512x128] @ link_emb[1:]^T -> replicated x5 into pred_hard
    mma_gemm128_kernel<<<dim3(Bq / 128, NEq / 64), 256, GK_TOTAL>>>(
        p_query, EDq, link_emb + EDq, EDq, nullptr, out, (long long)NEq * PLq, Bq, EDq, 0, PLq, NEq);
}